// round 5
// baseline (speedup 1.0000x reference)
#include <cuda_runtime.h>
#include <cuda_bf16.h>

// DifferentiableSMMPC: u = 0 is a fixed point of the reference iteration
// (Q_u = 2*R*0 = 0 -> k = 0 -> u stays 0), so the output u_traj[:, 0] is an
// exact (2048, 128) fp32 zero block; the only work is zero-filling d_out.
//
// R2: vec4 kernel, grid=256 -> 4.93us (kernel 3.74us)
// R3: cudaMemsetAsync graph node -> 6.88us (memset node overhead; reverted)
// R4: single wave, grid=128x512 -> 4.58us (kernel 3.46us). Floor-limited:
//     launch front-end + CTA rollout dominates (T_ovh ~5000 cyc).
// R5: halve CTA count and drop the bounds check. 64 blocks x 512 threads x
//     2 STG.128 each exactly covers 65536 float4 (1 MiB). Guarded fallback
//     kernel only for non-exact sizes (not taken for this shape).

__global__ __launch_bounds__(512, 1)
void smmpc_zero_fill_exact(float4* __restrict__ out) {
    // 2 stores per thread, block-contiguous: [bid*1024 + tid] and [+512]
    int base = blockIdx.x * 1024 + threadIdx.x;
    const float4 z = make_float4(0.f, 0.f, 0.f, 0.f);
    out[base]       = z;
    out[base + 512] = z;
}

__global__ void smmpc_zero_fill_guarded(float* __restrict__ out, int n) {
    int i = blockIdx.x * blockDim.x + threadIdx.x;
    if (i < n) out[i] = 0.f;
}

extern "C" void kernel_launch(void* const* d_in, const int* in_sizes, int n_in,
                              void* d_out, int out_size) {
    (void)d_in; (void)in_sizes; (void)n_in;

    float* out = (float*)d_out;
    int n_vec4 = out_size / 4;               // 65536 for the (2048,128) output
    const int per_block_vec4 = 512 * 2;      // 1024 float4 per CTA

    if ((out_size & 3) == 0 && n_vec4 % per_block_vec4 == 0) {
        int blocks = n_vec4 / per_block_vec4;               // 64
        smmpc_zero_fill_exact<<<blocks, 512>>>((float4*)out);
    } else {
        smmpc_zero_fill_guarded<<<(out_size + 511) / 512, 512>>>(out, out_size);
    }
}